// round 17
// baseline (speedup 1.0000x reference)
#include <cuda_runtime.h>

// Problem constants
#define NB   8
#define CCH  20
#define HH_  64
#define WW_  2048
#define HW   (HH_ * WW_)
#define TOT  (NB * CCH * HW)

// Tiling: each block: 10 channels x 4 rows x 128 output cols (shifted +2)
#define CC   10
#define HT   4
#define HT2  8            // HT + 4 halo rows
#define WVAL 132          // staged cols: w0 .. w0+131
#define WSTR 136          // padded row stride (floats)

// smem: poisoned xyz tile only
#define SMEM_FLOATS (3 * HT2 * WSTR)               // 3264
#define SMEM_BYTES  (SMEM_FLOATS * 4)              // 13056

#define POISON 1e18f

__global__ __launch_bounds__(128, 6)
void lcxyz_kernel(const float* __restrict__ xyz,
                  const float* __restrict__ softmax,
                  const unsigned int* __restrict__ mask,  // 4-byte 0/1: word!=0
                  float* __restrict__ out)
{
    extern __shared__ float smem[];
    float* s_xyz = smem;   // [3][HT2][WSTR]; slot idx <-> col w0+idx; poisoned if masked/out-of-frame

    const int tid  = threadIdx.x;
    const int wid  = tid >> 5;
    const int lane = tid & 31;

    const int bx   = blockIdx.x;
    const int w0   = (bx == 16) ? -4 : (bx << 7);   // extra strip covers cols 0..1
    const int n    = blockIdx.z >> 1;
    const int c0   = (blockIdx.z & 1) * CC;
    const int h0   = blockIdx.y * HT;

    // ---- stage xyz with poison masking: slot (r, idx) = source (h0+r-2, w0+idx) ----
    #pragma unroll 1
    for (int r = wid; r < HT2; r += 4) {
        const int hh = h0 + r - 2;
        const bool hv = (hh >= 0) && (hh < HH_);
        const unsigned int* msrc = mask + (size_t)(n * HH_ + hh) * WW_;
        const float* x0 = xyz + ((size_t)(n * 3 + 0) * HH_ + hh) * WW_;
        const float* x1 = x0 + (size_t)HW;
        const float* x2 = x1 + (size_t)HW;
        float* d0 = s_xyz + (0 * HT2 + r) * WSTR;
        float* d1 = s_xyz + (1 * HT2 + r) * WSTR;
        float* d2 = s_xyz + (2 * HT2 + r) * WSTR;
        #pragma unroll
        for (int idx = lane; idx < WVAL; idx += 32) {
            const int ww = w0 + idx;
            const bool ok = hv && ((unsigned)ww < (unsigned)WW_);
            if (ok && msrc[ww] != 0u) {
                d0[idx] = x0[ww];
                d1[idx] = x1[ww];
                d2[idx] = x2[ww];
            } else {
                d0[idx] = POISON;
                d1[idx] = POISON;
                d2[idx] = POISON;
            }
        }
    }

    // ---- thread geometry: outputs at cols gc..gc+3, row gh ----
    const int ty = wid;
    const int wl = lane << 2;        // window slots wl..wl+7 (two aligned quads)
    const int gc = w0 + 2 + wl;      // first output col (may be <0 or >=WW_ at edge blocks)
    const int gh = h0 + ty;

    // ---- center xyz from GLOBAL (always real, even if masked) ----
    float xc0[4], xc1[4], xc2[4];
    {
        const size_t cb = ((size_t)(n * 3) * HH_ + gh) * WW_;
        if (gc >= 0 && gc + 3 < WW_) {
            // 8B-aligned float2 pairs
            float2 a0 = *(const float2*)&xyz[cb + gc];
            float2 a1 = *(const float2*)&xyz[cb + gc + 2];
            float2 b0 = *(const float2*)&xyz[cb + HW + gc];
            float2 b1 = *(const float2*)&xyz[cb + HW + gc + 2];
            float2 c0v = *(const float2*)&xyz[cb + 2 * (size_t)HW + gc];
            float2 c1v = *(const float2*)&xyz[cb + 2 * (size_t)HW + gc + 2];
            xc0[0]=a0.x; xc0[1]=a0.y; xc0[2]=a1.x; xc0[3]=a1.y;
            xc1[0]=b0.x; xc1[1]=b0.y; xc1[2]=b1.x; xc1[3]=b1.y;
            xc2[0]=c0v.x; xc2[1]=c0v.y; xc2[2]=c1v.x; xc2[3]=c1v.y;
        } else {
            // edge lanes of edge blocks only; clamped (outputs there are never stored)
            #pragma unroll
            for (int o = 0; o < 4; ++o) {
                int g = min(max(gc + o, 0), WW_ - 1);
                xc0[o] = xyz[cb + g];
                xc1[o] = xyz[cb + HW + g];
                xc2[o] = xyz[cb + 2 * (size_t)HW + g];
            }
        }
    }

    float acc[CC][4];
    #pragma unroll
    for (int c = 0; c < CC; ++c)
        #pragma unroll
        for (int o = 0; o < 4; ++o) acc[c][o] = 0.0f;

    __syncthreads();

    #pragma unroll 1
    for (int di = 0; di < 5; ++di) {
        const int r = ty + di;

        // xyz window: slots wl..wl+7, 3 channels (6 x LDS.128)
        float xv0[8], xv1[8], xv2[8];
        {
            const float4* p = (const float4*)&s_xyz[(0 * HT2 + r) * WSTR + wl];
            float4 a = p[0], b = p[1];
            xv0[0]=a.x; xv0[1]=a.y; xv0[2]=a.z; xv0[3]=a.w;
            xv0[4]=b.x; xv0[5]=b.y; xv0[6]=b.z; xv0[7]=b.w;
        }
        {
            const float4* p = (const float4*)&s_xyz[(1 * HT2 + r) * WSTR + wl];
            float4 a = p[0], b = p[1];
            xv1[0]=a.x; xv1[1]=a.y; xv1[2]=a.z; xv1[3]=a.w;
            xv1[4]=b.x; xv1[5]=b.y; xv1[6]=b.z; xv1[7]=b.w;
        }
        {
            const float4* p = (const float4*)&s_xyz[(2 * HT2 + r) * WSTR + wl];
            float4 a = p[0], b = p[1];
            xv2[0]=a.x; xv2[1]=a.y; xv2[2]=a.z; xv2[3]=a.w;
            xv2[4]=b.x; xv2[5]=b.y; xv2[6]=b.z; xv2[7]=b.w;
        }

        // 20 weights: exp(-d2/2); poisoned sources give exactly 0.
        // tap (o,dj) uses slot wl+o+dj  <->  col w0+wl+o+dj = gc+o+dj-2  ✓
        float wgt[4][5];
        #pragma unroll
        for (int dj = 0; dj < 5; ++dj) {
            #pragma unroll
            for (int o = 0; o < 4; ++o) {
                float dx = xv0[o + dj] - xc0[o];
                float dy = xv1[o + dj] - xc1[o];
                float dz = xv2[o + dj] - xc2[o];
                float d2 = dx * dx + dy * dy + dz * dz;
                wgt[o][dj] = __expf(-0.5f * d2);
            }
        }

        // source row clamped into frame (out-of-frame taps have wgt==0)
        const int rg  = gh + di - 2;
        const int hcl = min(max(rg, 0), HH_ - 1);
        const int base0 = ((n * CCH + c0) * HH_ + hcl) * WW_ + w0 + wl; // aligned quad

        // 10 channels: 2 aligned LDG.128 + 20 FFMA each
        #pragma unroll
        for (int c = 0; c < CC; ++c) {
            const int base = base0 + c * HW;
            int i0 = base;
            int i2 = base + 4;
            if (c == 0)      i0 = max(i0, 0);        // only first chunk/channel can underflow
            if (c == CC - 1) i2 = min(i2, TOT - 4);  // only last can overflow
            float4 a = *(const float4*)&softmax[i0];
            float4 b = *(const float4*)&softmax[i2];
            float s[8];
            s[0]=a.x; s[1]=a.y; s[2]=a.z; s[3]=a.w;
            s[4]=b.x; s[5]=b.y; s[6]=b.z; s[7]=b.w;
            #pragma unroll
            for (int o = 0; o < 4; ++o) {
                #pragma unroll
                for (int dj = 0; dj < 5; ++dj)
                    acc[c][o] += wgt[o][dj] * s[o + dj];
            }
        }
    }

    // ---- store: 2 predicated float2 per channel (8B-aligned) ----
    const bool pL = (gc >= 0) && (gc + 1 < WW_);      // pair (gc, gc+1)
    const bool pR = (gc + 2 >= 0) && (gc + 3 < WW_);  // pair (gc+2, gc+3)
    #pragma unroll
    for (int c = 0; c < CC; ++c) {
        const size_t ob = ((size_t)(n * CCH + c0 + c) * HH_ + gh) * WW_;
        if (pL) *(float2*)&out[ob + gc]     = make_float2(acc[c][0], acc[c][1]);
        if (pR) *(float2*)&out[ob + gc + 2] = make_float2(acc[c][2], acc[c][3]);
    }
}

extern "C" void kernel_launch(void* const* d_in, const int* in_sizes, int n_in,
                              void* d_out, int out_size)
{
    const float*        xyz  = (const float*)d_in[0];
    const float*        sm   = (const float*)d_in[1];
    const unsigned int* mask = (const unsigned int*)d_in[2];
    float*              out  = (float*)d_out;

    (void)in_sizes; (void)n_in; (void)out_size;

    // 17 x-blocks: 16 main tiles (+2 col shift) + 1 strip covering cols 0..1
    dim3 grid(17, HH_ / HT, NB * 2);   // 17 x 16 x 16 = 4352 blocks
    lcxyz_kernel<<<grid, 128, SMEM_BYTES>>>(xyz, sm, mask, out);
}